// round 8
// baseline (speedup 1.0000x reference)
#include <cuda_runtime.h>
#include <math.h>

#define NB 4
#define NPTS0 4096
#define STEPS 10
#define NEWP 1152
#define GDIM 256
#define HDIM 128
#define KSEL 64
#define NMAX (NPTS0 + STEPS*NEWP)   // 15616
#define NNEW (STEPS*NEWP)           // 11520
#define MAXE 15                     // ceil(14464/1024)

typedef unsigned long long ull;

// ---------------- device state (no allocations allowed) ----------------
__device__ __align__(16) float g_canvas[NB*NMAX*3];
__device__ __align__(16) float g_h2[NB*4096*128];
__device__ __align__(16) float g_pre[NB*128*NMAX];    // layout [b][j][i]
__device__ float g_gfeat[NB*GDIM];
__device__ float g_h[2][NB*HDIM];     // double-buffered by step parity
__device__ float g_c[2][NB*HDIM];
__device__ float g_ctr[NB*8];         // [b][0:3]=center, [3:6]=patch_feat
__device__ float g_base[NB*128];
__device__ __align__(16) float g_spart[4*NB*NMAX];   // per-j-group score partials
__device__ unsigned g_xmin[4*NB*16384];
__device__ float g_accum[4];
__device__ int   g_flag[STEPS*NB];

// ---------------- packed f32x2 helpers (FFMA2 path) ----------------
__device__ __forceinline__ ull pk(float lo, float hi){
    ull r; asm("mov.b64 %0,{%1,%2};" : "=l"(r) : "f"(lo), "f"(hi)); return r;
}
__device__ __forceinline__ void upk(ull v, float& lo, float& hi){
    asm("mov.b64 {%0,%1},%2;" : "=f"(lo), "=f"(hi) : "l"(v));
}
__device__ __forceinline__ ull fma2(ull a, ull b, ull c){
    ull d; asm("fma.rn.f32x2 %0,%1,%2,%3;" : "=l"(d) : "l"(a), "l"(b), "l"(c)); return d;
}
__device__ __forceinline__ ull mul2(ull a, ull b){
    ull d; asm("mul.rn.f32x2 %0,%1,%2;" : "=l"(d) : "l"(a), "l"(b)); return d;
}

__device__ __forceinline__ void atomicMaxF(float* addr, float val){
    int* ai = (int*)addr;
    int old = *ai;
    while (__int_as_float(old) < val){
        int assumed = old;
        old = atomicCAS(ai, assumed, __float_as_int(val));
        if (old == assumed) break;
    }
}

// float <-> order-preserving sortable uint
__device__ __forceinline__ unsigned f2s(float f){
    unsigned u = __float_as_uint(f);
    return u ^ ((unsigned)(((int)u) >> 31) | 0x80000000u);
}
__device__ __forceinline__ float s2f(unsigned s){
    unsigned u = (s & 0x80000000u) ? (s ^ 0x80000000u) : ~s;
    return __uint_as_float(u);
}

// OP=0 sum, OP=1 max. All threads participate; result broadcast.
template<int OP>
__device__ __forceinline__ float blockReduceT(float v){
    __shared__ float buf[32];
    #pragma unroll
    for (int o=16;o;o>>=1){
        float other = __shfl_down_sync(0xffffffffu, v, o);
        v = OP ? fmaxf(v, other) : v + other;
    }
    int w = threadIdx.x >> 5, l = threadIdx.x & 31, nw = blockDim.x >> 5;
    __syncthreads();
    if (l == 0) buf[w] = v;
    __syncthreads();
    if (w == 0){
        v = (l < nw) ? buf[l] : (OP ? -INFINITY : 0.f);
        #pragma unroll
        for (int o=16;o;o>>=1){
            float other = __shfl_down_sync(0xffffffffu, v, o);
            v = OP ? fmaxf(v, other) : v + other;
        }
        if (l == 0) buf[0] = v;
    }
    __syncthreads();
    return buf[0];
}

// ---------------- init ----------------
__global__ void k_init(const float* __restrict__ pts){
    int idx = blockIdx.x*blockDim.x + threadIdx.x;
    int total = NB*NPTS0*3;
    if (idx < total){
        int b = idx/(NPTS0*3); int r = idx%(NPTS0*3);
        g_canvas[b*NMAX*3 + r] = pts[idx];
    }
    if (idx < NB*HDIM){ g_h[0][idx]=0.f; g_c[0][idx]=0.f; }
    if (idx < NB*GDIM) g_gfeat[idx] = -INFINITY;
    if (idx < 4) g_accum[idx]=0.f;
    if (idx < STEPS*NB) g_flag[idx]=0;
    if (idx < 4*NB*16384) g_xmin[idx] = 0xFFFFFFFFu;
}

// ---------------- fused encoder layer1+layer2 + attention "pre" cache ----------
// grid (seg/64, NB), 256 threads. Phase A: enc1 into smem sA (transposed) + g_pre.
// Phase B: enc2 GEMM (16ty x 16tx, tile 4pts x 8cols) -> g_h2 (segment-local rows).
__global__ void k_enc12(int e0,
                        const float* __restrict__ w1, const float* __restrict__ b1,
                        const float* __restrict__ aw1,
                        const float* __restrict__ w2, const float* __restrict__ b2){
    extern __shared__ float sm[];
    float* sA  = sm;            // [64 k][65]
    float* sW2 = sm + 64*65;    // [64 k][128]
    int b = blockIdx.y, t = threadIdx.x;
    int p0 = blockIdx.x*64;     // segment-local base
    for (int q=t; q<2048; q+=256) ((float4*)sW2)[q] = ((const float4*)w2)[q];
    // Phase A: enc1
    {
        int il = t>>2;          // local point 0..63
        int gi = e0 + p0 + il;  // global canvas index
        int part = t & 3;
        const float* p = &g_canvas[(b*NMAX+gi)*3];
        float x = p[0], y = p[1], z = p[2];
        #pragma unroll
        for (int j=0;j<16;j++){
            int c = part*16 + j;
            float v = b1[c] + x*w1[c] + y*w1[64+c] + z*w1[128+c];
            sA[c*65 + il] = fmaxf(v, 0.f);
        }
        #pragma unroll
        for (int j=0;j<32;j++){
            int c = part*32 + j;
            float v = x*aw1[c] + y*aw1[128+c] + z*aw1[256+c];
            g_pre[(b*128 + c)*NMAX + gi] = v;
        }
    }
    __syncthreads();
    // Phase B: enc2
    int ty = t>>4, tx = t&15;
    ull acc[4][4];
    #pragma unroll
    for (int i=0;i<4;i++)
        #pragma unroll
        for (int j=0;j<4;j++) acc[i][j]=0ull;
    #pragma unroll 2
    for (int k=0;k<64;k++){
        ull ad[4];
        #pragma unroll
        for (int i=0;i<4;i++){ float a = sA[k*65+4*ty+i]; ad[i] = pk(a,a); }
        ull wp[4];
        #pragma unroll
        for (int j=0;j<4;j++) wp[j] = *(ull*)&sW2[k*128 + 8*tx + 2*j];
        #pragma unroll
        for (int i=0;i<4;i++)
            #pragma unroll
            for (int j=0;j<4;j++) acc[i][j] = fma2(ad[i], wp[j], acc[i][j]);
    }
    float bb[8];
    #pragma unroll
    for (int j=0;j<8;j++) bb[j] = b2[8*tx+j];
    #pragma unroll
    for (int i=0;i<4;i++){
        int pt = p0 + 4*ty + i;
        float r[8];
        #pragma unroll
        for (int j=0;j<4;j++){
            float lo,hi; upk(acc[i][j], lo, hi);
            r[2*j]   = fmaxf(lo + bb[2*j],   0.f);
            r[2*j+1] = fmaxf(hi + bb[2*j+1], 0.f);
        }
        *(float4*)&g_h2[(b*4096+pt)*128 + 8*tx]     = make_float4(r[0],r[1],r[2],r[3]);
        *(float4*)&g_h2[(b*4096+pt)*128 + 8*tx + 4] = make_float4(r[4],r[5],r[6],r[7]);
    }
}

// ---------------- encoder layer3 + running max (dual-smem) --------
// grid (seg/128, 4 colblocks, NB), 256 threads = 16ty(8pts) x 16tx(4cols)
__global__ void k_enc3(const float* __restrict__ w3, const float* __restrict__ b3){
    extern __shared__ float sm[];
    float* sA = sm;              // [128 k][130]
    float* sW = sm + 128*130;    // [128 k][64]
    int b = blockIdx.z, cb = blockIdx.y, t = threadIdx.x;
    int p0 = blockIdx.x*128;
    for (int q=t; q<128*32; q+=256){
        int pt = q>>5, k4 = (q&31)<<2;
        float4 v = *(const float4*)&g_h2[(b*4096+p0+pt)*128 + k4];
        sA[(k4  )*130+pt]=v.x; sA[(k4+1)*130+pt]=v.y;
        sA[(k4+2)*130+pt]=v.z; sA[(k4+3)*130+pt]=v.w;
    }
    for (int q=t; q<2048; q+=256){
        int k = q>>4, c4 = (q&15)<<2;
        *(float4*)&sW[k*64 + c4] = *(const float4*)&w3[k*256 + cb*64 + c4];
    }
    __syncthreads();
    int ty = t>>4, tx = t&15;
    ull acc[4][4];   // [pt-pair][col]
    #pragma unroll
    for (int i=0;i<4;i++)
        #pragma unroll
        for (int j=0;j<4;j++) acc[i][j]=0ull;
    #pragma unroll 2
    for (int k=0;k<128;k++){
        ull ap[4];
        #pragma unroll
        for (int i=0;i<4;i++) ap[i] = *(ull*)&sA[k*130 + 8*ty + 2*i];
        float4 w = *(float4*)&sW[k*64 + 4*tx];
        ull wd[4] = { pk(w.x,w.x), pk(w.y,w.y), pk(w.z,w.z), pk(w.w,w.w) };
        #pragma unroll
        for (int i=0;i<4;i++)
            #pragma unroll
            for (int j=0;j<4;j++) acc[i][j] = fma2(ap[i], wd[j], acc[i][j]);
    }
    float m[4];
    #pragma unroll
    for (int j=0;j<4;j++){
        float best = -INFINITY;
        #pragma unroll
        for (int i=0;i<4;i++){
            float lo,hi; upk(acc[i][j], lo, hi);
            best = fmaxf(best, fmaxf(lo,hi));
        }
        m[j] = best + b3[cb*64 + 4*tx + j];
    }
    __syncthreads();
    float* red = sA;   // reuse
    #pragma unroll
    for (int j=0;j<4;j++) red[ty*64 + 4*tx + j] = m[j];
    __syncthreads();
    if (t < 64){
        float v = red[t];
        #pragma unroll
        for (int r=1;r<16;r++) v = fmaxf(v, red[r*64 + t]);
        atomicMaxF(&g_gfeat[b*GDIM + cb*64 + t], v);
    }
}

// ---------------- attention base (per step, per batch) ----------------
// grid NB, 1024 threads: 8 k-groups x 128 outputs
__global__ void k_attbase(int r,
                          const float* __restrict__ aw1, const float* __restrict__ ab1){
    __shared__ float part[8][128];
    int b = blockIdx.x, t = threadIdx.x;
    int kg = t >> 7, tt = t & 127;
    const float* gf = &g_gfeat[b*GDIM];
    const float* hh = &g_h[r][b*HDIM];
    float s = 0.f;
    int k0 = kg*48;
    #pragma unroll 4
    for (int k=k0; k<k0+48; k++){
        float a = (k < 256) ? gf[k] : hh[k-256];
        s += a * aw1[(3+k)*128 + tt];
    }
    part[kg][tt] = s;
    __syncthreads();
    if (t < 128){
        float v = ab1[t];
        #pragma unroll
        for (int q=0;q<8;q++) v += part[q][t];
        g_base[b*128 + t] = v;
    }
}

// ---------------- attention scores: j-group partials, float4 streaming -------
// grid ((N+511)/512, 4 jgroups, NB), 128 threads; 4 pts/thread.
// Writes partial relu-sums to g_spart plane jg (summed in k_tailref).
// ab2 omitted: softmax is shift-invariant.
__global__ void k_att(int N, const float* __restrict__ aw2){
    __shared__ float s_base[32], s_w2[32];
    int b = blockIdx.z, jg = blockIdx.y, t = threadIdx.x;
    if (t < 32){
        s_base[t] = g_base[b*128 + jg*32 + t];
        s_w2[t]   = aw2[jg*32 + t];
    }
    __syncthreads();
    int i0 = blockIdx.x*512 + 4*t;
    if (i0 >= N) return;
    const float* pr = &g_pre[(b*128 + jg*32)*NMAX + i0];
    float a0=0.f, a1=0.f, a2=0.f, a3=0.f;
    #pragma unroll 8
    for (int j=0;j<32;j++){
        float4 p = *(const float4*)&pr[j*NMAX];
        float bj = s_base[j], wj = s_w2[j];
        a0 += fmaxf(p.x + bj, 0.f) * wj;
        a1 += fmaxf(p.y + bj, 0.f) * wj;
        a2 += fmaxf(p.z + bj, 0.f) * wj;
        a3 += fmaxf(p.w + bj, 0.f) * wj;
    }
    *(float4*)&g_spart[(jg*NB + b)*NMAX + i0] = make_float4(a0,a1,a2,a3);
}

// ---------------- fused tail + LSTM + refine ----------------
// grid (8, NB), 1024 threads. Block x==0: softmax/center/top-K/LSTM -> flag.
// Blocks x>0 spin on flag (all 32 blocks co-resident on 148 SMs -> safe).
// Then ALL blocks do the refine MLP (432 outputs each).
__global__ void __launch_bounds__(1024) k_tailref(int N, int r, int s,
    const float* __restrict__ wih, const float* __restrict__ whh,
    const float* __restrict__ bih, const float* __restrict__ bhh,
    const float* __restrict__ rw1, const float* __restrict__ rb1,
    const float* __restrict__ rw2, const float* __restrict__ rb2){
    __shared__ unsigned s_hist[256];
    __shared__ int s_ibc[4];
    __shared__ float s_in[262], s_g[512], s_hold[128];
    __shared__ float s_h2[128], s_r[128];
    int b = blockIdx.y, bx = blockIdx.x, t = threadIdx.x;
    int* flag = &g_flag[s*NB + b];

    if (bx == 0){
        const float* p0 = &g_spart[(0*NB + b)*NMAX];
        const float* p1 = &g_spart[(1*NB + b)*NMAX];
        const float* p2 = &g_spart[(2*NB + b)*NMAX];
        const float* p3 = &g_spart[(3*NB + b)*NMAX];
        const float* cv = &g_canvas[b*NMAX*3];
        float vs[MAXE]; unsigned du[MAXE];
        float mx = -INFINITY;
        #pragma unroll
        for (int e=0;e<MAXE;e++){
            int i = t + e*1024;
            if (i < N){
                vs[e] = (p0[i]+p1[i]) + (p2[i]+p3[i]);
                mx = fmaxf(mx, vs[e]);
            }
        }
        mx = blockReduceT<1>(mx);
        float es=0.f, cx=0.f, cy=0.f, cz=0.f;
        #pragma unroll
        for (int e=0;e<MAXE;e++){
            int i = t + e*1024;
            if (i < N){
                float ex = expf(vs[e]-mx);
                es += ex;
                cx += ex*cv[3*i]; cy += ex*cv[3*i+1]; cz += ex*cv[3*i+2];
            }
        }
        es = blockReduceT<0>(es);
        cx = blockReduceT<0>(cx); cy = blockReduceT<0>(cy); cz = blockReduceT<0>(cz);
        float ctr0 = cx/es, ctr1 = cy/es, ctr2 = cz/es;
        #pragma unroll
        for (int e=0;e<MAXE;e++){
            int i = t + e*1024;
            if (i < N){
                float dx=cv[3*i]-ctr0, dy=cv[3*i+1]-ctr1, dz=cv[3*i+2]-ctr2;
                du[e] = __float_as_uint(dx*dx + dy*dy + dz*dz);
            }
        }
        unsigned prefix = 0; int krem = KSEL;
        for (int rd=0; rd<4; rd++){
            int shift = 24 - 8*rd;
            unsigned maskhi = (rd==0) ? 0u : (0xFFFFFFFFu << (shift+8));
            __syncthreads();
            if (t < 256) s_hist[t] = 0u;
            __syncthreads();
            #pragma unroll
            for (int e=0;e<MAXE;e++){
                int i = t + e*1024;
                if (i < N){
                    unsigned u = du[e];
                    if ((u & maskhi) == prefix) atomicAdd(&s_hist[(u>>shift)&255], 1u);
                }
            }
            __syncthreads();
            if (t == 0){
                unsigned cum = 0; int sel = 255;
                for (int bin=0;bin<256;bin++){
                    unsigned c = s_hist[bin];
                    if (cum + c >= (unsigned)krem){ sel = bin; break; }
                    cum += c;
                }
                s_ibc[0] = sel; s_ibc[1] = krem - (int)cum;
            }
            __syncthreads();
            prefix |= ((unsigned)s_ibc[0]) << shift;
            krem = s_ibc[1];
        }
        __syncthreads();
        if (t == 0) s_ibc[2] = 0;
        __syncthreads();
        float sx=0.f, sy=0.f, sz=0.f;
        #pragma unroll
        for (int e=0;e<MAXE;e++){
            int i = t + e*1024;
            if (i < N){
                unsigned u = du[e];
                bool take = false;
                if (u < prefix) take = true;
                else if (u == prefix){
                    int pos = atomicAdd(&s_ibc[2], 1);
                    if (pos < krem) take = true;
                }
                if (take){ sx += cv[3*i]; sy += cv[3*i+1]; sz += cv[3*i+2]; }
            }
        }
        sx = blockReduceT<0>(sx); sy = blockReduceT<0>(sy); sz = blockReduceT<0>(sz);
        float pf0 = sx/(float)KSEL - ctr0;
        float pf1 = sy/(float)KSEL - ctr1;
        float pf2 = sz/(float)KSEL - ctr2;
        if (t == 0){
            g_ctr[b*8+0]=ctr0; g_ctr[b*8+1]=ctr1; g_ctr[b*8+2]=ctr2;
            g_ctr[b*8+3]=pf0;  g_ctr[b*8+4]=pf1;  g_ctr[b*8+5]=pf2;
        }
        // LSTM
        if (t < 256) s_in[t] = g_gfeat[b*GDIM + t];
        else if (t == 256) s_in[256] = ctr0;
        else if (t == 257) s_in[257] = ctr1;
        else if (t == 258) s_in[258] = ctr2;
        else if (t == 259) s_in[259] = pf0;
        else if (t == 260) s_in[260] = pf1;
        else if (t == 261) s_in[261] = pf2;
        if (t < 128) s_hold[t] = g_h[r][b*HDIM + t];
        __syncthreads();
        if (t < 512){
            float g = bih[t] + bhh[t];
            #pragma unroll 8
            for (int k=0;k<262;k++) g += s_in[k]*__ldg(&wih[k*512 + t]);
            #pragma unroll 8
            for (int k=0;k<128;k++) g += s_hold[k]*__ldg(&whh[k*512 + t]);
            s_g[t] = g;
        }
        __syncthreads();
        if (t < 128){
            float gi = s_g[t], gf = s_g[128+t], gg = s_g[256+t], go = s_g[384+t];
            float si = 1.f/(1.f+expf(-gi));
            float sf = 1.f/(1.f+expf(-gf));
            float so = 1.f/(1.f+expf(-go));
            float cn = sf*g_c[r][b*HDIM+t] + si*tanhf(gg);
            float hn = so*tanhf(cn);
            g_c[1-r][b*HDIM+t] = cn;
            g_h[1-r][b*HDIM+t] = hn;
        }
        __threadfence();
        __syncthreads();
        if (t == 0) atomicExch(flag, 1);
    } else {
        if (t == 0){
            while (atomicAdd(flag, 0) == 0) __nanosleep(100);
        }
        __syncthreads();
    }
    // ---- refine (all blocks) ----
    if (t < 128) s_h2[t] = g_h[1-r][b*HDIM + t];
    __syncthreads();
    if (t < 128){
        float v = rb1[t];
        #pragma unroll 4
        for (int k=0;k<128;k++) v += s_h2[k]*rw1[k*128 + t];
        s_r[t] = fmaxf(v, 0.f);
    }
    __syncthreads();
    int j = bx*432 + t;
    if (t < 432 && j < NEWP*3){
        float v = rb2[j];
        #pragma unroll 8
        for (int k=0;k<128;k++) v += s_r[k]*__ldg(&rw2[k*(NEWP*3) + j]);
        int d = j % 3, pt = j / 3;
        g_canvas[(b*NMAX + N + pt)*3 + d] = v*0.02f + g_ctr[b*8 + d];
    }
}

// ---------------- chamfer: packed-FFMA2 pairwise min (full chip) ----------------
__global__ void k_cham2(const float* __restrict__ gt){
    __shared__ __align__(16) float s_yx[128];
    __shared__ __align__(16) float s_yy[128];
    __shared__ __align__(16) float s_yz[128];
    __shared__ __align__(16) float s_n[128];
    int z = blockIdx.z; int mode = z >> 2; int b = z & 3;
    const float* cin = &g_canvas[b*NMAX*3];
    const float* gb  = &gt[b*NPTS0*3];
    const float *X, *Y; int nx, ny;
    if (mode == 0){ X=cin;          Y=gb;          nx=NPTS0; ny=NPTS0; }
    else if (mode == 1){ X=gb;      Y=cin;         nx=NPTS0; ny=NPTS0; }
    else if (mode == 2){ X=cin+NPTS0*3; Y=gb;      nx=NNEW;  ny=NPTS0; }
    else { X=gb;          Y=cin+NPTS0*3;           nx=NPTS0; ny=NNEW;  }
    int x0 = blockIdx.x*512;
    int y0 = blockIdx.y*2048;
    if (x0 >= nx || y0 >= ny) return;
    int yend = min(y0 + 2048, ny);
    int t = threadIdx.x;

    ull xd[4][3]; bool val[4]; float me[4], mo[4];
    #pragma unroll
    for (int i=0;i<4;i++){
        int xi = x0 + i*128 + t;
        val[i] = xi < nx;
        int cl = val[i] ? xi : 0;
        float a=X[cl*3], bb=X[cl*3+1], c=X[cl*3+2];
        xd[i][0]=pk(a,a); xd[i][1]=pk(bb,bb); xd[i][2]=pk(c,c);
        me[i]=INFINITY; mo[i]=INFINITY;
    }
    ull c_m2 = pk(-2.f,-2.f);

    for (int yb=y0; yb<yend; yb+=128){
        __syncthreads();
        {
            int yi = yb + t;
            float a=Y[yi*3], bb=Y[yi*3+1], c=Y[yi*3+2];
            s_yx[t]=a; s_yy[t]=bb; s_yz[t]=c;
            s_n[t]=a*a + bb*bb + c*c;
        }
        __syncthreads();
        #pragma unroll 4
        for (int j=0;j<64;j++){
            ull yx = ((ull*)s_yx)[j];
            ull yy = ((ull*)s_yy)[j];
            ull yz = ((ull*)s_yz)[j];
            ull nn = ((ull*)s_n)[j];
            #pragma unroll
            for (int i=0;i<4;i++){
                ull dot = fma2(xd[i][2], yz, fma2(xd[i][1], yy, mul2(xd[i][0], yx)));
                ull d   = fma2(dot, c_m2, nn);
                float lo,hi; upk(d, lo, hi);
                me[i] = fminf(me[i], lo);
                mo[i] = fminf(mo[i], hi);
            }
        }
    }
    #pragma unroll
    for (int i=0;i<4;i++){
        if (val[i]){
            float m = fminf(me[i], mo[i]);
            atomicMin(&g_xmin[(mode*NB + b)*16384 + x0 + i*128 + t], f2s(m));
        }
    }
}

// sum pass: accum[mode] = sum_x (|x|^2 + min-part)
__global__ void k_chamsum(const float* __restrict__ gt){
    int mode = blockIdx.z, b = blockIdx.y, t = threadIdx.x;
    const float* cin = &g_canvas[b*NMAX*3];
    const float* gb  = &gt[b*NPTS0*3];
    const float* X; int nx;
    if (mode == 0){ X=cin; nx=NPTS0; }
    else if (mode == 1){ X=gb; nx=NPTS0; }
    else if (mode == 2){ X=cin+NPTS0*3; nx=NNEW; }
    else { X=gb; nx=NPTS0; }
    int xi = blockIdx.x*256 + t;
    float v = 0.f;
    if (xi < nx){
        float f = s2f(g_xmin[(mode*NB + b)*16384 + xi]);
        float a=X[xi*3], bb=X[xi*3+1], c=X[xi*3+2];
        v = f + a*a + bb*bb + c*c;
    }
    v = blockReduceT<0>(v);
    if (t == 0) atomicAdd(&g_accum[mode], v);
}

__global__ void k_final(float* out){
    if (threadIdx.x == 0){
        float a0 = g_accum[0] / (float)(NB*NPTS0);
        float a1 = g_accum[1] / (float)(NB*NPTS0);
        float a2 = g_accum[2] / (float)(NB*NNEW);
        float a3 = g_accum[3] / (float)(NB*NPTS0);
        out[0] = 0.1f*(a0 + a1) + 1.0f*(a2 + a3);
    }
}

// ---------------- host ----------------
extern "C" void kernel_launch(void* const* d_in, const int* in_sizes, int n_in,
                              void* d_out, int out_size){
    const float* points   = (const float*)d_in[0];
    const float* gt       = (const float*)d_in[1];
    const float* enc_w1   = (const float*)d_in[2];
    const float* enc_b1   = (const float*)d_in[3];
    const float* enc_w2   = (const float*)d_in[4];
    const float* enc_b2   = (const float*)d_in[5];
    const float* enc_w3   = (const float*)d_in[6];
    const float* enc_b3   = (const float*)d_in[7];
    const float* att_w1   = (const float*)d_in[8];
    const float* att_b1   = (const float*)d_in[9];
    const float* att_w2   = (const float*)d_in[10];
    const float* att_b2   = (const float*)d_in[11];
    const float* lstm_wih = (const float*)d_in[12];
    const float* lstm_whh = (const float*)d_in[13];
    const float* lstm_bih = (const float*)d_in[14];
    const float* lstm_bhh = (const float*)d_in[15];
    const float* ref_w1   = (const float*)d_in[16];
    const float* ref_b1   = (const float*)d_in[17];
    const float* ref_w2   = (const float*)d_in[18];
    const float* ref_b2   = (const float*)d_in[19];

    const int SM12 = (64*65 + 64*128)*4;    // 49408
    const int SM3  = (128*130 + 128*64)*4;  // 99328
    cudaFuncSetAttribute(k_enc12, cudaFuncAttributeMaxDynamicSharedMemorySize, SM12);
    cudaFuncSetAttribute(k_enc3,  cudaFuncAttributeMaxDynamicSharedMemorySize, SM3);

    k_init<<<256,1024>>>(points);

    int encoded = 0;
    for (int s=0; s<STEPS; s++){
        int N   = NPTS0 + NEWP*s;
        int seg = N - encoded;
        int e0  = encoded;
        int r   = s & 1;
        dim3 g1(seg/64, NB);
        k_enc12<<<g1,256,SM12>>>(e0, enc_w1, enc_b1, att_w1, enc_w2, enc_b2);
        dim3 g3(seg/128, 4, NB);
        k_enc3<<<g3,256,SM3>>>(enc_w3, enc_b3);
        encoded = N;
        k_attbase<<<NB,1024>>>(r, att_w1, att_b1);
        dim3 ga((N+511)/512, 4, NB);
        k_att<<<ga,128>>>(N, att_w2);
        k_tailref<<<dim3(8,NB),1024>>>(N, r, s, lstm_wih, lstm_whh, lstm_bih, lstm_bhh,
                                       ref_w1, ref_b1, ref_w2, ref_b2);
    }
    k_cham2<<<dim3(23,6,16),128>>>(gt);
    k_chamsum<<<dim3(45,NB,4),256>>>(gt);
    k_final<<<1,32>>>((float*)d_out);
}

// round 9
// speedup vs baseline: 1.5721x; 1.5721x over previous
#include <cuda_runtime.h>
#include <math.h>

#define NB 4
#define NPTS0 4096
#define STEPS 10
#define NEWP 1152
#define GDIM 256
#define HDIM 128
#define KSEL 64
#define NMAX (NPTS0 + STEPS*NEWP)   // 15616
#define NNEW (STEPS*NEWP)           // 11520
#define MAXE 15                     // ceil(14464/1024)

typedef unsigned long long ull;

// ---------------- device state (no allocations allowed) ----------------
__device__ __align__(16) float g_canvas[NB*NMAX*3];
__device__ __align__(16) float g_h2[NB*4096*128];
__device__ __align__(16) float g_pre[NB*128*NMAX];    // layout [b][j][i]
__device__ float g_gfeat[NB*GDIM];
__device__ float g_h[2][NB*HDIM];     // double-buffered by step parity
__device__ float g_c[2][NB*HDIM];
__device__ float g_ctr[NB*8];         // [b][0:3]=center, [3:6]=patch_feat
__device__ __align__(16) float g_spart[4*NB*NMAX];   // per-j-group score partials
__device__ unsigned g_xmin[4*NB*16384];
__device__ float g_accum[4];
__device__ int   g_flag[STEPS*NB];

// ---------------- packed f32x2 helpers (FFMA2 path) ----------------
__device__ __forceinline__ ull pk(float lo, float hi){
    ull r; asm("mov.b64 %0,{%1,%2};" : "=l"(r) : "f"(lo), "f"(hi)); return r;
}
__device__ __forceinline__ void upk(ull v, float& lo, float& hi){
    asm("mov.b64 {%0,%1},%2;" : "=f"(lo), "=f"(hi) : "l"(v));
}
__device__ __forceinline__ ull fma2(ull a, ull b, ull c){
    ull d; asm("fma.rn.f32x2 %0,%1,%2,%3;" : "=l"(d) : "l"(a), "l"(b), "l"(c)); return d;
}
__device__ __forceinline__ ull mul2(ull a, ull b){
    ull d; asm("mul.rn.f32x2 %0,%1,%2;" : "=l"(d) : "l"(a), "l"(b)); return d;
}

__device__ __forceinline__ void atomicMaxF(float* addr, float val){
    int* ai = (int*)addr;
    int old = *ai;
    while (__int_as_float(old) < val){
        int assumed = old;
        old = atomicCAS(ai, assumed, __float_as_int(val));
        if (old == assumed) break;
    }
}

// float <-> order-preserving sortable uint
__device__ __forceinline__ unsigned f2s(float f){
    unsigned u = __float_as_uint(f);
    return u ^ ((unsigned)(((int)u) >> 31) | 0x80000000u);
}
__device__ __forceinline__ float s2f(unsigned s){
    unsigned u = (s & 0x80000000u) ? (s ^ 0x80000000u) : ~s;
    return __uint_as_float(u);
}

// OP=0 sum, OP=1 max. All threads participate; result broadcast.
template<int OP>
__device__ __forceinline__ float blockReduceT(float v){
    __shared__ float buf[32];
    #pragma unroll
    for (int o=16;o;o>>=1){
        float other = __shfl_down_sync(0xffffffffu, v, o);
        v = OP ? fmaxf(v, other) : v + other;
    }
    int w = threadIdx.x >> 5, l = threadIdx.x & 31, nw = blockDim.x >> 5;
    __syncthreads();
    if (l == 0) buf[w] = v;
    __syncthreads();
    if (w == 0){
        v = (l < nw) ? buf[l] : (OP ? -INFINITY : 0.f);
        #pragma unroll
        for (int o=16;o;o>>=1){
            float other = __shfl_down_sync(0xffffffffu, v, o);
            v = OP ? fmaxf(v, other) : v + other;
        }
        if (l == 0) buf[0] = v;
    }
    __syncthreads();
    return buf[0];
}

// ---------------- init ----------------
__global__ void k_init(const float* __restrict__ pts){
    int idx = blockIdx.x*blockDim.x + threadIdx.x;
    int total = NB*NPTS0*3;
    if (idx < total){
        int b = idx/(NPTS0*3); int r = idx%(NPTS0*3);
        g_canvas[b*NMAX*3 + r] = pts[idx];
    }
    if (idx < NB*HDIM){ g_h[0][idx]=0.f; g_c[0][idx]=0.f; }
    if (idx < NB*GDIM) g_gfeat[idx] = -INFINITY;
    if (idx < 4) g_accum[idx]=0.f;
    if (idx < STEPS*NB) g_flag[idx]=0;
    if (idx < 4*NB*16384) g_xmin[idx] = 0xFFFFFFFFu;
}

// ---------------- fused encoder layer1+layer2 + attention "pre" cache ----------
// grid (seg/64, NB), 256 threads. Phase A: enc1 into smem sA (transposed) + g_pre.
// Phase B: enc2 GEMM (16ty x 16tx, tile 4pts x 8cols) -> g_h2 (segment-local rows).
__global__ void k_enc12(int e0,
                        const float* __restrict__ w1, const float* __restrict__ b1,
                        const float* __restrict__ aw1,
                        const float* __restrict__ w2, const float* __restrict__ b2){
    extern __shared__ float sm[];
    float* sA  = sm;            // [64 k][65]
    float* sW2 = sm + 64*65;    // [64 k][128]
    int b = blockIdx.y, t = threadIdx.x;
    int p0 = blockIdx.x*64;     // segment-local base
    for (int q=t; q<2048; q+=256) ((float4*)sW2)[q] = ((const float4*)w2)[q];
    // Phase A: enc1
    {
        int il = t>>2;          // local point 0..63
        int gi = e0 + p0 + il;  // global canvas index
        int part = t & 3;
        const float* p = &g_canvas[(b*NMAX+gi)*3];
        float x = p[0], y = p[1], z = p[2];
        #pragma unroll
        for (int j=0;j<16;j++){
            int c = part*16 + j;
            float v = b1[c] + x*w1[c] + y*w1[64+c] + z*w1[128+c];
            sA[c*65 + il] = fmaxf(v, 0.f);
        }
        #pragma unroll
        for (int j=0;j<32;j++){
            int c = part*32 + j;
            float v = x*aw1[c] + y*aw1[128+c] + z*aw1[256+c];
            g_pre[(b*128 + c)*NMAX + gi] = v;
        }
    }
    __syncthreads();
    // Phase B: enc2
    int ty = t>>4, tx = t&15;
    ull acc[4][4];
    #pragma unroll
    for (int i=0;i<4;i++)
        #pragma unroll
        for (int j=0;j<4;j++) acc[i][j]=0ull;
    #pragma unroll 2
    for (int k=0;k<64;k++){
        ull ad[4];
        #pragma unroll
        for (int i=0;i<4;i++){ float a = sA[k*65+4*ty+i]; ad[i] = pk(a,a); }
        ull wp[4];
        #pragma unroll
        for (int j=0;j<4;j++) wp[j] = *(ull*)&sW2[k*128 + 8*tx + 2*j];
        #pragma unroll
        for (int i=0;i<4;i++)
            #pragma unroll
            for (int j=0;j<4;j++) acc[i][j] = fma2(ad[i], wp[j], acc[i][j]);
    }
    float bb[8];
    #pragma unroll
    for (int j=0;j<8;j++) bb[j] = b2[8*tx+j];
    #pragma unroll
    for (int i=0;i<4;i++){
        int pt = p0 + 4*ty + i;
        float r[8];
        #pragma unroll
        for (int j=0;j<4;j++){
            float lo,hi; upk(acc[i][j], lo, hi);
            r[2*j]   = fmaxf(lo + bb[2*j],   0.f);
            r[2*j+1] = fmaxf(hi + bb[2*j+1], 0.f);
        }
        *(float4*)&g_h2[(b*4096+pt)*128 + 8*tx]     = make_float4(r[0],r[1],r[2],r[3]);
        *(float4*)&g_h2[(b*4096+pt)*128 + 8*tx + 4] = make_float4(r[4],r[5],r[6],r[7]);
    }
}

// ---------------- encoder layer3 + running max (dual-smem) --------
// grid (seg/128, 4 colblocks, NB), 256 threads = 16ty(8pts) x 16tx(4cols)
__global__ void k_enc3(const float* __restrict__ w3, const float* __restrict__ b3){
    extern __shared__ float sm[];
    float* sA = sm;              // [128 k][130]
    float* sW = sm + 128*130;    // [128 k][64]
    int b = blockIdx.z, cb = blockIdx.y, t = threadIdx.x;
    int p0 = blockIdx.x*128;
    for (int q=t; q<128*32; q+=256){
        int pt = q>>5, k4 = (q&31)<<2;
        float4 v = *(const float4*)&g_h2[(b*4096+p0+pt)*128 + k4];
        sA[(k4  )*130+pt]=v.x; sA[(k4+1)*130+pt]=v.y;
        sA[(k4+2)*130+pt]=v.z; sA[(k4+3)*130+pt]=v.w;
    }
    for (int q=t; q<2048; q+=256){
        int k = q>>4, c4 = (q&15)<<2;
        *(float4*)&sW[k*64 + c4] = *(const float4*)&w3[k*256 + cb*64 + c4];
    }
    __syncthreads();
    int ty = t>>4, tx = t&15;
    ull acc[4][4];   // [pt-pair][col]
    #pragma unroll
    for (int i=0;i<4;i++)
        #pragma unroll
        for (int j=0;j<4;j++) acc[i][j]=0ull;
    #pragma unroll 2
    for (int k=0;k<128;k++){
        ull ap[4];
        #pragma unroll
        for (int i=0;i<4;i++) ap[i] = *(ull*)&sA[k*130 + 8*ty + 2*i];
        float4 w = *(float4*)&sW[k*64 + 4*tx];
        ull wd[4] = { pk(w.x,w.x), pk(w.y,w.y), pk(w.z,w.z), pk(w.w,w.w) };
        #pragma unroll
        for (int i=0;i<4;i++)
            #pragma unroll
            for (int j=0;j<4;j++) acc[i][j] = fma2(ap[i], wd[j], acc[i][j]);
    }
    float m[4];
    #pragma unroll
    for (int j=0;j<4;j++){
        float best = -INFINITY;
        #pragma unroll
        for (int i=0;i<4;i++){
            float lo,hi; upk(acc[i][j], lo, hi);
            best = fmaxf(best, fmaxf(lo,hi));
        }
        m[j] = best + b3[cb*64 + 4*tx + j];
    }
    __syncthreads();
    float* red = sA;   // reuse
    #pragma unroll
    for (int j=0;j<4;j++) red[ty*64 + 4*tx + j] = m[j];
    __syncthreads();
    if (t < 64){
        float v = red[t];
        #pragma unroll
        for (int r=1;r<16;r++) v = fmaxf(v, red[r*64 + t]);
        atomicMaxF(&g_gfeat[b*GDIM + cb*64 + t], v);
    }
}

// ---------------- attention scores: in-block base + j-group partials ---------
// grid ((N+511)/512, 4 jgroups, NB), 128 threads; 4 pts/thread, float4 stream.
// base[32] computed cooperatively (4 threads/output x 96 MACs, shfl reduce).
// ab2 omitted: softmax is shift-invariant.
__global__ void k_att(int N, int r,
                      const float* __restrict__ aw1, const float* __restrict__ ab1,
                      const float* __restrict__ aw2){
    __shared__ float s_in[384];
    __shared__ float s_base[32], s_w2[32];
    int b = blockIdx.z, jg = blockIdx.y, t = threadIdx.x;
    // stage gfeat || h
    s_in[t]       = g_gfeat[b*GDIM + t];
    s_in[128 + t] = g_gfeat[b*GDIM + 128 + t];
    s_in[256 + t] = g_h[r][b*HDIM + t];
    if (t < 32) s_w2[t] = aw2[jg*32 + t];
    __syncthreads();
    // base: output jj = t>>2, partial part = t&3 over 96 k's each (384 = 4*96)
    {
        int jj = t >> 2, part = t & 3;
        int c  = jg*32 + jj;
        const float* col = &aw1[3*128 + c];   // rows 3.. map k -> (3+k)
        float s = 0.f;
        int k0 = part*96;
        #pragma unroll 8
        for (int k=k0; k<k0+96; k++)
            s += s_in[k] * col[k*128];
        s += __shfl_down_sync(0xffffffffu, s, 1);
        s += __shfl_down_sync(0xffffffffu, s, 2);
        if (part == 0) s_base[jj] = s + ab1[c];
    }
    __syncthreads();
    int i0 = blockIdx.x*512 + 4*t;
    if (i0 >= N) return;
    const float* pr = &g_pre[(b*128 + jg*32)*NMAX + i0];
    float a0=0.f, a1=0.f, a2=0.f, a3=0.f;
    #pragma unroll 8
    for (int j=0;j<32;j++){
        float4 p = *(const float4*)&pr[j*NMAX];
        float bj = s_base[j], wj = s_w2[j];
        a0 += fmaxf(p.x + bj, 0.f) * wj;
        a1 += fmaxf(p.y + bj, 0.f) * wj;
        a2 += fmaxf(p.z + bj, 0.f) * wj;
        a3 += fmaxf(p.w + bj, 0.f) * wj;
    }
    *(float4*)&g_spart[(jg*NB + b)*NMAX + i0] = make_float4(a0,a1,a2,a3);
}

// ---------------- fused tail + LSTM + refine ----------------
// grid (8, NB), 1024 threads. Block x==0: softmax/center/top-K/LSTM -> flag.
// Blocks x>0 spin on flag (all 32 blocks co-resident on 148 SMs -> safe).
// Then ALL blocks do the refine MLP (432 outputs each).
__global__ void __launch_bounds__(1024) k_tailref(int N, int r, int s,
    const float* __restrict__ wih, const float* __restrict__ whh,
    const float* __restrict__ bih, const float* __restrict__ bhh,
    const float* __restrict__ rw1, const float* __restrict__ rb1,
    const float* __restrict__ rw2, const float* __restrict__ rb2){
    __shared__ unsigned s_hist[256];
    __shared__ int s_ibc[4];
    __shared__ float s_in[262], s_g[512], s_hold[128];
    __shared__ float s_h2[128], s_r[128];
    int b = blockIdx.y, bx = blockIdx.x, t = threadIdx.x;
    int* flag = &g_flag[s*NB + b];

    if (bx == 0){
        const float* p0 = &g_spart[(0*NB + b)*NMAX];
        const float* p1 = &g_spart[(1*NB + b)*NMAX];
        const float* p2 = &g_spart[(2*NB + b)*NMAX];
        const float* p3 = &g_spart[(3*NB + b)*NMAX];
        const float* cv = &g_canvas[b*NMAX*3];
        float vs[MAXE]; unsigned du[MAXE];
        float mx = -INFINITY;
        #pragma unroll
        for (int e=0;e<MAXE;e++){
            int i = t + e*1024;
            if (i < N){
                vs[e] = (p0[i]+p1[i]) + (p2[i]+p3[i]);
                mx = fmaxf(mx, vs[e]);
            }
        }
        mx = blockReduceT<1>(mx);
        float es=0.f, cx=0.f, cy=0.f, cz=0.f;
        #pragma unroll
        for (int e=0;e<MAXE;e++){
            int i = t + e*1024;
            if (i < N){
                float ex = expf(vs[e]-mx);
                es += ex;
                cx += ex*cv[3*i]; cy += ex*cv[3*i+1]; cz += ex*cv[3*i+2];
            }
        }
        es = blockReduceT<0>(es);
        cx = blockReduceT<0>(cx); cy = blockReduceT<0>(cy); cz = blockReduceT<0>(cz);
        float ctr0 = cx/es, ctr1 = cy/es, ctr2 = cz/es;
        #pragma unroll
        for (int e=0;e<MAXE;e++){
            int i = t + e*1024;
            if (i < N){
                float dx=cv[3*i]-ctr0, dy=cv[3*i+1]-ctr1, dz=cv[3*i+2]-ctr2;
                du[e] = __float_as_uint(dx*dx + dy*dy + dz*dz);
            }
        }
        unsigned prefix = 0; int krem = KSEL;
        for (int rd=0; rd<4; rd++){
            int shift = 24 - 8*rd;
            unsigned maskhi = (rd==0) ? 0u : (0xFFFFFFFFu << (shift+8));
            __syncthreads();
            if (t < 256) s_hist[t] = 0u;
            __syncthreads();
            #pragma unroll
            for (int e=0;e<MAXE;e++){
                int i = t + e*1024;
                if (i < N){
                    unsigned u = du[e];
                    if ((u & maskhi) == prefix) atomicAdd(&s_hist[(u>>shift)&255], 1u);
                }
            }
            __syncthreads();
            if (t == 0){
                unsigned cum = 0; int sel = 255;
                for (int bin=0;bin<256;bin++){
                    unsigned c = s_hist[bin];
                    if (cum + c >= (unsigned)krem){ sel = bin; break; }
                    cum += c;
                }
                s_ibc[0] = sel; s_ibc[1] = krem - (int)cum;
            }
            __syncthreads();
            prefix |= ((unsigned)s_ibc[0]) << shift;
            krem = s_ibc[1];
        }
        __syncthreads();
        if (t == 0) s_ibc[2] = 0;
        __syncthreads();
        float sx=0.f, sy=0.f, sz=0.f;
        #pragma unroll
        for (int e=0;e<MAXE;e++){
            int i = t + e*1024;
            if (i < N){
                unsigned u = du[e];
                bool take = false;
                if (u < prefix) take = true;
                else if (u == prefix){
                    int pos = atomicAdd(&s_ibc[2], 1);
                    if (pos < krem) take = true;
                }
                if (take){ sx += cv[3*i]; sy += cv[3*i+1]; sz += cv[3*i+2]; }
            }
        }
        sx = blockReduceT<0>(sx); sy = blockReduceT<0>(sy); sz = blockReduceT<0>(sz);
        float pf0 = sx/(float)KSEL - ctr0;
        float pf1 = sy/(float)KSEL - ctr1;
        float pf2 = sz/(float)KSEL - ctr2;
        if (t == 0){
            g_ctr[b*8+0]=ctr0; g_ctr[b*8+1]=ctr1; g_ctr[b*8+2]=ctr2;
            g_ctr[b*8+3]=pf0;  g_ctr[b*8+4]=pf1;  g_ctr[b*8+5]=pf2;
        }
        // LSTM
        if (t < 256) s_in[t] = g_gfeat[b*GDIM + t];
        else if (t == 256) s_in[256] = ctr0;
        else if (t == 257) s_in[257] = ctr1;
        else if (t == 258) s_in[258] = ctr2;
        else if (t == 259) s_in[259] = pf0;
        else if (t == 260) s_in[260] = pf1;
        else if (t == 261) s_in[261] = pf2;
        if (t < 128) s_hold[t] = g_h[r][b*HDIM + t];
        __syncthreads();
        if (t < 512){
            float g = bih[t] + bhh[t];
            #pragma unroll 8
            for (int k=0;k<262;k++) g += s_in[k]*__ldg(&wih[k*512 + t]);
            #pragma unroll 8
            for (int k=0;k<128;k++) g += s_hold[k]*__ldg(&whh[k*512 + t]);
            s_g[t] = g;
        }
        __syncthreads();
        if (t < 128){
            float gi = s_g[t], gf = s_g[128+t], gg = s_g[256+t], go = s_g[384+t];
            float si = 1.f/(1.f+expf(-gi));
            float sf = 1.f/(1.f+expf(-gf));
            float so = 1.f/(1.f+expf(-go));
            float cn = sf*g_c[r][b*HDIM+t] + si*tanhf(gg);
            float hn = so*tanhf(cn);
            g_c[1-r][b*HDIM+t] = cn;
            g_h[1-r][b*HDIM+t] = hn;
        }
        __threadfence();
        __syncthreads();
        if (t == 0) atomicExch(flag, 1);
    } else {
        if (t == 0){
            while (atomicAdd(flag, 0) == 0) __nanosleep(100);
        }
        __syncthreads();
    }
    // ---- refine (all blocks) ----
    if (t < 128) s_h2[t] = g_h[1-r][b*HDIM + t];
    __syncthreads();
    if (t < 128){
        float v = rb1[t];
        #pragma unroll 4
        for (int k=0;k<128;k++) v += s_h2[k]*rw1[k*128 + t];
        s_r[t] = fmaxf(v, 0.f);
    }
    __syncthreads();
    int j = bx*432 + t;
    if (t < 432 && j < NEWP*3){
        float v = rb2[j];
        #pragma unroll 8
        for (int k=0;k<128;k++) v += s_r[k]*__ldg(&rw2[k*(NEWP*3) + j]);
        int d = j % 3, pt = j / 3;
        g_canvas[(b*NMAX + N + pt)*3 + d] = v*0.02f + g_ctr[b*8 + d];
    }
}

// ---------------- chamfer: packed-FFMA2 pairwise min (full chip) ----------------
__global__ void k_cham2(const float* __restrict__ gt){
    __shared__ __align__(16) float s_yx[128];
    __shared__ __align__(16) float s_yy[128];
    __shared__ __align__(16) float s_yz[128];
    __shared__ __align__(16) float s_n[128];
    int z = blockIdx.z; int mode = z >> 2; int b = z & 3;
    const float* cin = &g_canvas[b*NMAX*3];
    const float* gb  = &gt[b*NPTS0*3];
    const float *X, *Y; int nx, ny;
    if (mode == 0){ X=cin;          Y=gb;          nx=NPTS0; ny=NPTS0; }
    else if (mode == 1){ X=gb;      Y=cin;         nx=NPTS0; ny=NPTS0; }
    else if (mode == 2){ X=cin+NPTS0*3; Y=gb;      nx=NNEW;  ny=NPTS0; }
    else { X=gb;          Y=cin+NPTS0*3;           nx=NPTS0; ny=NNEW;  }
    int x0 = blockIdx.x*512;
    int y0 = blockIdx.y*2048;
    if (x0 >= nx || y0 >= ny) return;
    int yend = min(y0 + 2048, ny);
    int t = threadIdx.x;

    ull xd[4][3]; bool val[4]; float me[4], mo[4];
    #pragma unroll
    for (int i=0;i<4;i++){
        int xi = x0 + i*128 + t;
        val[i] = xi < nx;
        int cl = val[i] ? xi : 0;
        float a=X[cl*3], bb=X[cl*3+1], c=X[cl*3+2];
        xd[i][0]=pk(a,a); xd[i][1]=pk(bb,bb); xd[i][2]=pk(c,c);
        me[i]=INFINITY; mo[i]=INFINITY;
    }
    ull c_m2 = pk(-2.f,-2.f);

    for (int yb=y0; yb<yend; yb+=128){
        __syncthreads();
        {
            int yi = yb + t;
            float a=Y[yi*3], bb=Y[yi*3+1], c=Y[yi*3+2];
            s_yx[t]=a; s_yy[t]=bb; s_yz[t]=c;
            s_n[t]=a*a + bb*bb + c*c;
        }
        __syncthreads();
        #pragma unroll 4
        for (int j=0;j<64;j++){
            ull yx = ((ull*)s_yx)[j];
            ull yy = ((ull*)s_yy)[j];
            ull yz = ((ull*)s_yz)[j];
            ull nn = ((ull*)s_n)[j];
            #pragma unroll
            for (int i=0;i<4;i++){
                ull dot = fma2(xd[i][2], yz, fma2(xd[i][1], yy, mul2(xd[i][0], yx)));
                ull d   = fma2(dot, c_m2, nn);
                float lo,hi; upk(d, lo, hi);
                me[i] = fminf(me[i], lo);
                mo[i] = fminf(mo[i], hi);
            }
        }
    }
    #pragma unroll
    for (int i=0;i<4;i++){
        if (val[i]){
            float m = fminf(me[i], mo[i]);
            atomicMin(&g_xmin[(mode*NB + b)*16384 + x0 + i*128 + t], f2s(m));
        }
    }
}

// sum pass: accum[mode] = sum_x (|x|^2 + min-part)
__global__ void k_chamsum(const float* __restrict__ gt){
    int mode = blockIdx.z, b = blockIdx.y, t = threadIdx.x;
    const float* cin = &g_canvas[b*NMAX*3];
    const float* gb  = &gt[b*NPTS0*3];
    const float* X; int nx;
    if (mode == 0){ X=cin; nx=NPTS0; }
    else if (mode == 1){ X=gb; nx=NPTS0; }
    else if (mode == 2){ X=cin+NPTS0*3; nx=NNEW; }
    else { X=gb; nx=NPTS0; }
    int xi = blockIdx.x*256 + t;
    float v = 0.f;
    if (xi < nx){
        float f = s2f(g_xmin[(mode*NB + b)*16384 + xi]);
        float a=X[xi*3], bb=X[xi*3+1], c=X[xi*3+2];
        v = f + a*a + bb*bb + c*c;
    }
    v = blockReduceT<0>(v);
    if (t == 0) atomicAdd(&g_accum[mode], v);
}

__global__ void k_final(float* out){
    if (threadIdx.x == 0){
        float a0 = g_accum[0] / (float)(NB*NPTS0);
        float a1 = g_accum[1] / (float)(NB*NPTS0);
        float a2 = g_accum[2] / (float)(NB*NNEW);
        float a3 = g_accum[3] / (float)(NB*NPTS0);
        out[0] = 0.1f*(a0 + a1) + 1.0f*(a2 + a3);
    }
}

// ---------------- host ----------------
extern "C" void kernel_launch(void* const* d_in, const int* in_sizes, int n_in,
                              void* d_out, int out_size){
    const float* points   = (const float*)d_in[0];
    const float* gt       = (const float*)d_in[1];
    const float* enc_w1   = (const float*)d_in[2];
    const float* enc_b1   = (const float*)d_in[3];
    const float* enc_w2   = (const float*)d_in[4];
    const float* enc_b2   = (const float*)d_in[5];
    const float* enc_w3   = (const float*)d_in[6];
    const float* enc_b3   = (const float*)d_in[7];
    const float* att_w1   = (const float*)d_in[8];
    const float* att_b1   = (const float*)d_in[9];
    const float* att_w2   = (const float*)d_in[10];
    const float* att_b2   = (const float*)d_in[11];
    const float* lstm_wih = (const float*)d_in[12];
    const float* lstm_whh = (const float*)d_in[13];
    const float* lstm_bih = (const float*)d_in[14];
    const float* lstm_bhh = (const float*)d_in[15];
    const float* ref_w1   = (const float*)d_in[16];
    const float* ref_b1   = (const float*)d_in[17];
    const float* ref_w2   = (const float*)d_in[18];
    const float* ref_b2   = (const float*)d_in[19];

    const int SM12 = (64*65 + 64*128)*4;    // 49408
    const int SM3  = (128*130 + 128*64)*4;  // 99328
    cudaFuncSetAttribute(k_enc12, cudaFuncAttributeMaxDynamicSharedMemorySize, SM12);
    cudaFuncSetAttribute(k_enc3,  cudaFuncAttributeMaxDynamicSharedMemorySize, SM3);

    k_init<<<256,1024>>>(points);

    int encoded = 0;
    for (int s=0; s<STEPS; s++){
        int N   = NPTS0 + NEWP*s;
        int seg = N - encoded;
        int e0  = encoded;
        int r   = s & 1;
        dim3 g1(seg/64, NB);
        k_enc12<<<g1,256,SM12>>>(e0, enc_w1, enc_b1, att_w1, enc_w2, enc_b2);
        dim3 g3(seg/128, 4, NB);
        k_enc3<<<g3,256,SM3>>>(enc_w3, enc_b3);
        encoded = N;
        dim3 ga((N+511)/512, 4, NB);
        k_att<<<ga,128>>>(N, r, att_w1, att_b1, att_w2);
        k_tailref<<<dim3(8,NB),1024>>>(N, r, s, lstm_wih, lstm_whh, lstm_bih, lstm_bhh,
                                       ref_w1, ref_b1, ref_w2, ref_b2);
    }
    k_cham2<<<dim3(23,6,16),128>>>(gt);
    k_chamsum<<<dim3(45,NB,4),256>>>(gt);
    k_final<<<1,32>>>((float*)d_out);
}